// round 16
// baseline (speedup 1.0000x reference)
#include <cuda_runtime.h>
#include <cstdint>

#define BB 2
#define N1 4096
#define N2 8192
#define NSPC 4            // cosine candidate splits (2048 each)
#define NSPE 8            // euclid splits
#define COSL 128          // cosine partial lists per query: NSPC*4 subs*8
#define KSEL 16
#define NGRP 6
#define NTHR (NGRP * 64)
#define QT 64
#define CT 64

// ---------------- scratch ----------------
__device__ __align__(16) float g_f1h [BB*N1*64];
__device__ __align__(16) float g_f1l [BB*N1*64];
__device__ __align__(16) float g_f2h [BB*N2*64];
__device__ __align__(16) float g_f2l [BB*N2*64];
__device__ __align__(16) float g_p2r [BB*N2*64];
__device__ __align__(16) float g_p2ro[BB*N2*64];
__device__ __align__(16) float g_p2z [BB*N2*64];
__device__ __align__(16) float g_gp1r[BB*N1*64];
__device__ __align__(16) float g_gp1z[BB*N1*64];
__device__ __align__(16) float g_p1o [BB*N1*64];
__device__ float g_cosv[BB*N1*COSL];
__device__ int   g_cosi[BB*N1*COSL];
__device__ float g_eucv[BB*N1*NSPE*8];
__device__ int   g_euci[BB*N1*NSPE*8];

// ---------------- helpers ----------------
__device__ __forceinline__ void fma2(unsigned long long& d, unsigned long long a, unsigned long long b) {
    asm("fma.rn.f32x2 %0, %1, %2, %0;" : "+l"(d) : "l"(a), "l"(b));
}
__device__ __forceinline__ float hsum2(unsigned long long v) {
    return __uint_as_float((unsigned)v) + __uint_as_float((unsigned)(v >> 32));
}
__device__ __forceinline__ float leaky(float x) { return fmaxf(x, 0.1f * x); }
__device__ __forceinline__ float sigm(float x) { return 1.f / (1.f + __expf(-x)); }
__device__ __forceinline__ float tf32_rna(float f) {
    uint32_t r;
    asm("cvt.rna.tf32.f32 %0, %1;" : "=r"(r) : "f"(f));
    return __uint_as_float(r);
}
__device__ __forceinline__ void mma_tf32(float (&c)[4],
    uint32_t a0, uint32_t a1, uint32_t a2, uint32_t a3, uint32_t b0, uint32_t b1) {
    asm volatile(
        "mma.sync.aligned.m16n8k8.row.col.f32.tf32.tf32.f32 "
        "{%0,%1,%2,%3}, {%4,%5,%6,%7}, {%8,%9}, {%0,%1,%2,%3};"
        : "+f"(c[0]), "+f"(c[1]), "+f"(c[2]), "+f"(c[3])
        : "r"(a0), "r"(a1), "r"(a2), "r"(a3), "r"(b0), "r"(b1));
}

__device__ __forceinline__ void top8_insert(float (&tv)[8], int (&ti)[8], float v, int j) {
    #pragma unroll
    for (int t = 0; t < 8; t++) {
        if (v > tv[t]) { float fv = tv[t]; int fj = ti[t]; tv[t] = v; ti[t] = j; v = fv; j = fj; }
    }
}

__device__ __forceinline__ void loadrow(const float* __restrict__ W, int o, ulonglong2 (&w)[16]) {
    const ulonglong2* p = (const ulonglong2*)(W + o * 68);
    #pragma unroll
    for (int i = 0; i < 16; i++) w[i] = p[i];
}
__device__ __forceinline__ float dotv64(const ulonglong2 (&w)[16], const float* __restrict__ v) {
    const ulonglong2* v2 = (const ulonglong2*)v;
    ulonglong2 x[8];
    unsigned long long a0 = 0ull, a1 = 0ull, a2 = 0ull, a3 = 0ull;
    #pragma unroll
    for (int i = 0; i < 8; i++) x[i] = v2[i];
    #pragma unroll
    for (int i = 0; i < 8; i += 2) {
        fma2(a0, w[i].x,     x[i].x);
        fma2(a1, w[i].y,     x[i].y);
        fma2(a2, w[i + 1].x, x[i + 1].x);
        fma2(a3, w[i + 1].y, x[i + 1].y);
    }
    #pragma unroll
    for (int i = 0; i < 8; i++) x[i] = v2[8 + i];
    #pragma unroll
    for (int i = 0; i < 8; i += 2) {
        fma2(a0, w[8 + i].x,     x[i].x);
        fma2(a1, w[8 + i].y,     x[i].y);
        fma2(a2, w[8 + i + 1].x, x[i + 1].x);
        fma2(a3, w[8 + i + 1].y, x[i + 1].y);
    }
    return (hsum2(a0) + hsum2(a1)) + (hsum2(a2) + hsum2(a3));
}
__device__ __forceinline__ float gdot64(const float* __restrict__ Wrow, const float* __restrict__ v) {
    const float4* w4 = (const float4*)Wrow;
    const float4* v4 = (const float4*)v;
    float a0 = 0.f, a1 = 0.f, a2 = 0.f, a3 = 0.f;
    #pragma unroll
    for (int i = 0; i < 16; i += 4) {
        float4 w = __ldg(&w4[i]);      float4 x = v4[i];
        a0 += w.x * x.x + w.y * x.y + w.z * x.z + w.w * x.w;
        float4 w1 = __ldg(&w4[i + 1]); float4 x1 = v4[i + 1];
        a1 += w1.x * x1.x + w1.y * x1.y + w1.z * x1.z + w1.w * x1.w;
        float4 w2 = __ldg(&w4[i + 2]); float4 x2 = v4[i + 2];
        a2 += w2.x * x2.x + w2.y * x2.y + w2.z * x2.z + w2.w * x2.w;
        float4 w3 = __ldg(&w4[i + 3]); float4 x3 = v4[i + 3];
        a3 += w3.x * x3.x + w3.y * x3.y + w3.z * x3.z + w3.w * x3.w;
    }
    return (a0 + a1) + (a2 + a3);
}

// ---------------- [0] normalize both knn tensors -> tf32 hi/lo splits ----------------
__global__ void k_norm_both(const float* __restrict__ knn1, const float* __restrict__ knn2,
                            float* __restrict__ f1h, float* __restrict__ f1l,
                            float* __restrict__ f2h, float* __restrict__ f2l) {
    __shared__ float s[64 * 65];
    __shared__ float inv[64];
    int bx = blockIdx.x, b = blockIdx.y;
    const float* src; float* dh; float* dl; int N, n0;
    if (bx < N1 / 64) { src = knn1; dh = f1h; dl = f1l; N = N1; n0 = bx * 64; }
    else              { src = knn2; dh = f2h; dl = f2l; N = N2; n0 = (bx - N1 / 64) * 64; }
    src += (size_t)b * 64 * N;
    for (int i = threadIdx.x; i < 4096; i += 256) {
        int c = i >> 6, n = i & 63;
        s[c * 65 + n] = src[(size_t)c * N + n0 + n];
    }
    __syncthreads();
    if (threadIdx.x < 64) {
        int n = threadIdx.x;
        float acc = 0.f;
        #pragma unroll
        for (int c = 0; c < 64; c++) { float v = s[c * 65 + n]; acc += v * v; }
        inv[n] = rsqrtf(acc + 1e-8f);
    }
    __syncthreads();
    size_t off = ((size_t)b * N + n0) * 64;
    for (int i = threadIdx.x; i < 4096; i += 256) {
        int n = i >> 6, c = i & 63;
        float f = s[c * 65 + n] * inv[n];
        float hi = tf32_rna(f);
        dh[off + n * 64 + c] = hi;
        dl[off + n * 64 + c] = f - hi;
    }
}

// ---------------- [1] cosine knn via split-tf32 mma ----------------
// block 256 thr = 8 warps (warpRow=wid&3 -> 16q band, warpCol=wid>>2 -> 32c band).
// Tile 64q x 64c; scores -> smem; 4 sub-scanners per query keep running top-8.
__global__ void __launch_bounds__(256, 2) k_cosmma() {
    extern __shared__ __align__(16) float cm[];
    float* sQh = cm;                 // 64*68
    float* sQl = sQh + QT * 68;
    float* sCh = sQl + QT * 68;      // 64*68
    float* sCl = sCh + CT * 68;
    float* sS  = sCl + CT * 68;      // 64*65

    int b = blockIdx.z, split = blockIdx.y, qt = blockIdx.x;
    int tid = threadIdx.x;
    int lane = tid & 31, wid = tid >> 5;
    int warpRow = wid & 3, warpCol = wid >> 2;
    int groupID = lane >> 2, tig = lane & 3;
    int qbase = warpRow * 16, cbase = warpCol * 32;

    // stage Q tile (hi/lo)
    {
        const float4* gh = (const float4*)(g_f1h + ((size_t)b * N1 + qt * QT) * 64);
        const float4* gl = (const float4*)(g_f1l + ((size_t)b * N1 + qt * QT) * 64);
        for (int i = tid; i < 1024; i += 256) {
            int row = i >> 4, col = (i & 15) * 4;
            *(float4*)&sQh[row * 68 + col] = gh[i];
            *(float4*)&sQl[row * 68 + col] = gl[i];
        }
    }

    float tv[8]; int ti[8];
    #pragma unroll
    for (int i = 0; i < 8; i++) { tv[i] = -1e30f; ti[i] = 0; }
    int myq = tid & 63, mysub = tid >> 6;

    const int CSPLIT = N2 / NSPC;    // 2048
    for (int ct = 0; ct < CSPLIT / CT; ct++) {   // 32 iterations
        int c0g = split * CSPLIT + ct * CT;
        __syncthreads();   // prev scan done; safe to overwrite sC/sS
        {
            const float4* gh = (const float4*)(g_f2h + ((size_t)b * N2 + c0g) * 64);
            const float4* gl = (const float4*)(g_f2l + ((size_t)b * N2 + c0g) * 64);
            for (int i = tid; i < 1024; i += 256) {
                int row = i >> 4, col = (i & 15) * 4;
                *(float4*)&sCh[row * 68 + col] = gh[i];
                *(float4*)&sCl[row * 68 + col] = gl[i];
            }
        }
        __syncthreads();

        float acc[4][4];
        #pragma unroll
        for (int nt = 0; nt < 4; nt++)
            #pragma unroll
            for (int j = 0; j < 4; j++) acc[nt][j] = 0.f;

        #pragma unroll
        for (int k0 = 0; k0 < 64; k0 += 8) {
            uint32_t ah0 = __float_as_uint(sQh[(qbase + groupID) * 68 + k0 + tig]);
            uint32_t ah1 = __float_as_uint(sQh[(qbase + groupID + 8) * 68 + k0 + tig]);
            uint32_t ah2 = __float_as_uint(sQh[(qbase + groupID) * 68 + k0 + tig + 4]);
            uint32_t ah3 = __float_as_uint(sQh[(qbase + groupID + 8) * 68 + k0 + tig + 4]);
            uint32_t al0 = __float_as_uint(sQl[(qbase + groupID) * 68 + k0 + tig]);
            uint32_t al1 = __float_as_uint(sQl[(qbase + groupID + 8) * 68 + k0 + tig]);
            uint32_t al2 = __float_as_uint(sQl[(qbase + groupID) * 68 + k0 + tig + 4]);
            uint32_t al3 = __float_as_uint(sQl[(qbase + groupID + 8) * 68 + k0 + tig + 4]);
            #pragma unroll
            for (int nt = 0; nt < 4; nt++) {
                int nb = cbase + nt * 8;
                uint32_t bh0 = __float_as_uint(sCh[(nb + groupID) * 68 + k0 + tig]);
                uint32_t bh1 = __float_as_uint(sCh[(nb + groupID) * 68 + k0 + tig + 4]);
                uint32_t bl0 = __float_as_uint(sCl[(nb + groupID) * 68 + k0 + tig]);
                uint32_t bl1 = __float_as_uint(sCl[(nb + groupID) * 68 + k0 + tig + 4]);
                mma_tf32(acc[nt], ah0, ah1, ah2, ah3, bh0, bh1);   // hi*hi
                mma_tf32(acc[nt], ah0, ah1, ah2, ah3, bl0, bl1);   // hi*lo
                mma_tf32(acc[nt], al0, al1, al2, al3, bh0, bh1);   // lo*hi
            }
        }

        // store scores: sS[q][c], row stride 65
        #pragma unroll
        for (int nt = 0; nt < 4; nt++) {
            int nb = cbase + nt * 8;
            sS[(qbase + groupID) * 65 + nb + 2 * tig]         = acc[nt][0];
            sS[(qbase + groupID) * 65 + nb + 2 * tig + 1]     = acc[nt][1];
            sS[(qbase + groupID + 8) * 65 + nb + 2 * tig]     = acc[nt][2];
            sS[(qbase + groupID + 8) * 65 + nb + 2 * tig + 1] = acc[nt][3];
        }
        __syncthreads();

        // scan: thread handles (query myq, candidates mysub*16..+16)
        #pragma unroll
        for (int i = 0; i < 16; i++) {
            int cc = mysub * 16 + i;
            float v = sS[myq * 65 + cc];
            if (v > tv[7]) top8_insert(tv, ti, v, c0g + cc);
        }
    }

    int q = qt * QT + myq;
    size_t base = ((size_t)b * N1 + q) * COSL + (split * 4 + mysub) * 8;
    #pragma unroll
    for (int t = 0; t < 8; t++) { g_cosv[base + t] = tv[t]; g_cosi[base + t] = ti[t]; }
}

// ---------------- [2] euclid knn partials (proven loop) ----------------
__global__ void __launch_bounds__(256) k_eucknn(const float* __restrict__ xyz1, const float* __restrict__ xyz2) {
    __shared__ float sx[1024], sy[1024], sz[1024];
    int b = blockIdx.z, split = blockIdx.y;
    int q = blockIdx.x * 256 + threadIdx.x;
    int j0 = split * 1024;
    const float* x2 = xyz2 + (size_t)b * 3 * N2;
    for (int i = threadIdx.x; i < 1024; i += 256) {
        sx[i] = x2[j0 + i]; sy[i] = x2[N2 + j0 + i]; sz[i] = x2[2 * N2 + j0 + i];
    }
    __syncthreads();
    const float* x1 = xyz1 + (size_t)b * 3 * N1;
    float qx = x1[q], qy = x1[N1 + q], qz = x1[2 * N1 + q];
    float tv[8]; int ti[8];
    #pragma unroll
    for (int i = 0; i < 8; i++) { tv[i] = -1e30f; ti[i] = 0; }
    for (int cc = 0; cc < 1024; cc++) {
        float dx = sx[cc] - qx, dy = sy[cc] - qy, dz = sz[cc] - qz;
        float d = -(dx * dx + dy * dy + dz * dz);
        if (d > tv[7]) top8_insert(tv, ti, d, j0 + cc);
    }
    size_t base = (((size_t)b * N1 + q) * NSPE + split) * 8;
    #pragma unroll
    for (int t = 0; t < 8; t++) { g_eucv[base + t] = tv[t]; g_euci[base + t] = ti[t]; }
}

// ---------------- [3] all 6 projections in one launch ----------------
__global__ void __launch_bounds__(256) k_projall(
    const float* __restrict__ points1, const float* __restrict__ points2,
    const float* __restrict__ Wfr2, const float* __restrict__ Wfro2, const float* __restrict__ Wfz2,
    const float* __restrict__ Wfr,  const float* __restrict__ Wfz,   const float* __restrict__ Wfro,
    float* __restrict__ p2r, float* __restrict__ p2ro, float* __restrict__ p2z,
    float* __restrict__ gp1r, float* __restrict__ gp1z, float* __restrict__ p1o)
{
    __shared__ __align__(16) float s[64 * 68];
    __shared__ __align__(16) float Wsh[64 * 68];
    int m = blockIdx.z;
    const float* P; const float* W; float* out; int N;
    if (m < 3) {
        P = points2; N = N2;
        W   = (m == 0) ? Wfr2 : ((m == 1) ? Wfro2 : Wfz2);
        out = (m == 0) ? p2r  : ((m == 1) ? p2ro  : p2z);
    } else {
        P = points1; N = N1;
        W   = (m == 3) ? Wfr  : ((m == 4) ? Wfz  : Wfro);
        out = (m == 3) ? gp1r : ((m == 4) ? gp1z : p1o);
    }
    if (blockIdx.x * 64 >= N) return;
    int b = blockIdx.y;
    int n0 = blockIdx.x * 64;
    int t = threadIdx.x;
    for (int i = t; i < 4096; i += 256) {
        int c = i >> 6, n = i & 63;
        s[n * 68 + c] = P[((size_t)b * 64 + c) * N + n0 + n];
        Wsh[(i >> 6) * 68 + (i & 63)] = W[i];
    }
    __syncthreads();
    int o = t & 63, nb = t >> 6;
    float acc[16];
    #pragma unroll
    for (int j = 0; j < 16; j++) acc[j] = 0.f;
    const float4* w4 = (const float4*)(Wsh + o * 68);
    #pragma unroll
    for (int ci = 0; ci < 16; ci++) {
        float4 w = w4[ci];
        #pragma unroll
        for (int j = 0; j < 16; j++) {
            float4 v = ((const float4*)(s + (nb + 4 * j) * 68))[ci];
            acc[j] += w.x * v.x + w.y * v.y + w.z * v.z + w.w * v.w;
        }
    }
    float* dst = out + ((size_t)b * N + n0) * 64;
    #pragma unroll
    for (int j = 0; j < 16; j++)
        dst[(nb + 4 * j) * 64 + o] = acc[j];
}

// ---------------- [4] fused merge + GRU-mapping MLP (best config) ----------------
__global__ void __launch_bounds__(NTHR, 2) k_mlp(
    const float* __restrict__ xyz1, const float* __restrict__ xyz2,
    const float* __restrict__ Wr0, const float* __restrict__ br0,
    const float* __restrict__ Wr1, const float* __restrict__ br1,
    const float* __restrict__ Wr2, const float* __restrict__ br2,
    const float* __restrict__ Wz0, const float* __restrict__ bz0,
    const float* __restrict__ Wz1, const float* __restrict__ bz1,
    const float* __restrict__ Wz2, const float* __restrict__ bz2,
    const float* __restrict__ Wh0, const float* __restrict__ bh0,
    const float* __restrict__ Wh1, const float* __restrict__ bh1,
    const float* __restrict__ Wh2, const float* __restrict__ bh2,
    float* __restrict__ out)
{
    extern __shared__ __align__(16) float dsm[];
    float* WS   = dsm;            // streamed slab: 4352 floats
    float* GBUF = dsm + 4352;     // NGRP groups x 3 buffers x 16*64
    __shared__ int sIdx[NGRP * 16];

    int tid = threadIdx.x;
    int g = tid >> 6, o = tid & 63;

    int q = blockIdx.x * NGRP + g;
    if (q > BB * N1 - 1) q = BB * N1 - 1;
    int b = q >> 12, n = q & 4095;

    if ((o & 31) == 0) {
        int half = o >> 5;
        const float* pv = half ? g_eucv : g_cosv;
        const int*   pi = half ? g_euci : g_cosi;
        int cnt = half ? (NSPE * 8) : COSL;
        size_t base = (size_t)q * cnt;
        float tv[8]; int ti[8];
        #pragma unroll
        for (int i = 0; i < 8; i++) { tv[i] = -1e30f; ti[i] = 0; }
        #pragma unroll 4
        for (int i = 0; i < cnt; i++) {
            float v = pv[base + i];
            if (v > tv[7]) top8_insert(tv, ti, v, pi[base + i]);
        }
        #pragma unroll
        for (int t = 0; t < 8; t++) sIdx[g * 16 + half * 8 + t] = ti[t];
    }
    __syncthreads();

    float wr0x = Wr0[o * 3], wr0y = Wr0[o * 3 + 1], wr0z = Wr0[o * 3 + 2];
    float wz0x = Wz0[o * 3], wz0y = Wz0[o * 3 + 1], wz0z = Wz0[o * 3 + 2];
    float wh0x = Wh0[o * 3], wh0y = Wh0[o * 3 + 1], wh0z = Wh0[o * 3 + 2];
    float br0o = br0[o], br1o = br1[o], br2o = br2[o];
    float bz0o = bz0[o], bz1o = bz1[o];
    float bh0o = bh0[o], bh1o = bh1[o];
    size_t nb = (size_t)b * N1 + n;
    float gp1ro = g_gp1r[nb * 64 + o];
    float gp1zo = g_gp1z[nb * 64 + o];
    float p1oo  = g_p1o [nb * 64 + o];
    float x1x = xyz1[(b * 3 + 0) * N1 + n];
    float x1y = xyz1[(b * 3 + 1) * N1 + n];
    float x1z = xyz1[(b * 3 + 2) * N1 + n];

    float* T = GBUF + g * 3072;
    float* U = T + 1024;
    float* V = U + 1024;

    #pragma unroll 2
    for (int k = 0; k < KSEL; k++) {
        int j = sIdx[g * 16 + k];
        size_t gb = ((size_t)b * N2 + j) * 64 + o;
        float gr  = g_p2r [gb];
        float gro = g_p2ro[gb];
        float gz  = g_p2z [gb];
        float dx = __ldg(&xyz2[(b * 3 + 0) * N2 + j]) - x1x;
        float dy = __ldg(&xyz2[(b * 3 + 1) * N2 + j]) - x1y;
        float dz = __ldg(&xyz2[(b * 3 + 2) * N2 + j]) - x1z;
        T[k * 64 + o] = leaky(fmaf(wr0x, dx, fmaf(wr0y, dy, fmaf(wr0z, dz, br0o + gp1ro + gr))));
        U[k * 64 + o] = leaky(fmaf(wz0x, dx, fmaf(wz0y, dy, fmaf(wz0z, dz, bz0o + gp1zo + gro))));
        V[k * 64 + o] = fmaf(wh0x, dx, fmaf(wh0y, dy, fmaf(wh0z, dz, bh0o + gz)));
    }

    ulonglong2 w[16];
    float zmax = -1e30f, hmax = -1e30f;

    __syncthreads();
    for (int i = tid; i < 1024; i += NTHR) {
        float4 v = ((const float4*)Wz1)[i];
        int r = i * 4;
        *(float4*)&WS[(r >> 6) * 68 + (r & 63)] = v;
    }
    __syncthreads();
    loadrow(WS, o, w);
    #pragma unroll 1
    for (int k = 0; k < KSEL; k++)
        zmax = fmaxf(zmax, leaky(dotv64(w, U + k * 64) + bz1o));

    __syncthreads();
    for (int i = tid; i < 1024; i += NTHR) {
        float4 v = ((const float4*)Wr1)[i];
        int r = i * 4;
        *(float4*)&WS[(r >> 6) * 68 + (r & 63)] = v;
    }
    __syncthreads();
    loadrow(WS, o, w);
    #pragma unroll 1
    for (int k = 0; k < KSEL; k++)
        U[k * 64 + o] = leaky(dotv64(w, T + k * 64) + br1o);

    __syncthreads();
    for (int i = tid; i < 1024; i += NTHR) {
        float4 v = ((const float4*)Wr2)[i];
        int r = i * 4;
        *(float4*)&WS[(r >> 6) * 68 + (r & 63)] = v;
    }
    __syncthreads();
    loadrow(WS, o, w);
    #pragma unroll 1
    for (int k = 0; k < KSEL; k++) {
        float r = sigm(dotv64(w, U + k * 64) + br2o);
        V[k * 64 + o] = leaky(fmaf(r, p1oo, V[k * 64 + o]));
    }

    __syncthreads();
    for (int i = tid; i < 1024; i += NTHR) {
        float4 v = ((const float4*)Wh1)[i];
        int r = i * 4;
        *(float4*)&WS[(r >> 6) * 68 + (r & 63)] = v;
    }
    __syncthreads();
    loadrow(WS, o, w);
    #pragma unroll 1
    for (int k = 0; k < KSEL; k++)
        hmax = fmaxf(hmax, leaky(dotv64(w, V + k * 64) + bh1o));

    T[o] = zmax;
    T[64 + o] = hmax;
    __syncthreads();

    float z = sigm(gdot64(Wz2 + o * 64, T) + bz2[o]);
    float h = leaky(gdot64(Wh2 + o * 64, T + 64) + bh2[o]);
    out[((size_t)b * 64 + o) * N1 + n] = (1.f - z) * p1oo + z * h;
}

// ---------------- launch ----------------
extern "C" void kernel_launch(void* const* d_in, const int* in_sizes, int n_in,
                              void* d_out, int out_size) {
    (void)in_sizes; (void)n_in; (void)out_size;
    const float* xyz1    = (const float*)d_in[0];
    const float* xyz2    = (const float*)d_in[1];
    const float* points1 = (const float*)d_in[2];
    const float* points2 = (const float*)d_in[3];
    const float* knn1    = (const float*)d_in[4];
    const float* knn2    = (const float*)d_in[5];
    const float* Wfr   = (const float*)d_in[6];
    const float* Wfro  = (const float*)d_in[7];
    const float* Wfz   = (const float*)d_in[8];
    const float* Wfr2  = (const float*)d_in[9];
    const float* Wfro2 = (const float*)d_in[10];
    const float* Wfz2  = (const float*)d_in[11];
    const float* Wr0 = (const float*)d_in[12]; const float* br0 = (const float*)d_in[13];
    const float* Wr1 = (const float*)d_in[14]; const float* br1 = (const float*)d_in[15];
    const float* Wr2 = (const float*)d_in[16]; const float* br2 = (const float*)d_in[17];
    const float* Wz0 = (const float*)d_in[18]; const float* bz0 = (const float*)d_in[19];
    const float* Wz1 = (const float*)d_in[20]; const float* bz1 = (const float*)d_in[21];
    const float* Wz2 = (const float*)d_in[22]; const float* bz2 = (const float*)d_in[23];
    const float* Wh0 = (const float*)d_in[24]; const float* bh0 = (const float*)d_in[25];
    const float* Wh1 = (const float*)d_in[26]; const float* bh1 = (const float*)d_in[27];
    const float* Wh2 = (const float*)d_in[28]; const float* bh2 = (const float*)d_in[29];
    float* out = (float*)d_out;

    float *f1h, *f1l, *f2h, *f2l, *p2r, *p2ro, *p2z, *gp1r, *gp1z, *p1o;
    cudaGetSymbolAddress((void**)&f1h,  g_f1h);
    cudaGetSymbolAddress((void**)&f1l,  g_f1l);
    cudaGetSymbolAddress((void**)&f2h,  g_f2h);
    cudaGetSymbolAddress((void**)&f2l,  g_f2l);
    cudaGetSymbolAddress((void**)&p2r,  g_p2r);
    cudaGetSymbolAddress((void**)&p2ro, g_p2ro);
    cudaGetSymbolAddress((void**)&p2z,  g_p2z);
    cudaGetSymbolAddress((void**)&gp1r, g_gp1r);
    cudaGetSymbolAddress((void**)&gp1z, g_gp1z);
    cudaGetSymbolAddress((void**)&p1o,  g_p1o);

    const int MLP_SMEM = (4352 + NGRP * 3 * 1024) * 4;           // 91136 B
    const int MMA_SMEM = (4 * (QT * 68) + QT * 65) * 4;          // 86272 B
    cudaFuncSetAttribute(k_mlp,    cudaFuncAttributeMaxDynamicSharedMemorySize, MLP_SMEM);
    cudaFuncSetAttribute(k_cosmma, cudaFuncAttributeMaxDynamicSharedMemorySize, MMA_SMEM);

    // [0] normalize -> tf32 hi/lo splits
    k_norm_both<<<dim3((N1 + N2) / 64, BB), 256>>>(knn1, knn2, f1h, f1l, f2h, f2l);
    // [1] cosine knn via split-tf32 tensor cores
    k_cosmma<<<dim3(N1 / QT, NSPC, BB), 256, MMA_SMEM>>>();
    // [2] euclid knn partials
    k_eucknn<<<dim3(N1 / 256, NSPE, BB), 256>>>(xyz1, xyz2);
    // [3] all projections
    k_projall<<<dim3(N2 / 64, BB, 6), 256>>>(points1, points2,
        Wfr2, Wfro2, Wfz2, Wfr, Wfz, Wfro,
        p2r, p2ro, p2z, gp1r, gp1z, p1o);
    // [4] fused merge + GRU MLP
    int nblk = (BB * N1 + NGRP - 1) / NGRP;
    k_mlp<<<nblk, NTHR, MLP_SMEM>>>(
        xyz1, xyz2,
        Wr0, br0, Wr1, br1, Wr2, br2,
        Wz0, bz0, Wz1, bz1, Wz2, bz2,
        Wh0, bh0, Wh1, bh1, Wh2, bh2,
        out);
}

// round 17
// speedup vs baseline: 1.0523x; 1.0523x over previous
#include <cuda_runtime.h>
#include <cstdint>

#define BB 2
#define N1 4096
#define N2 8192
#define NSPLIT 8
#define KSEL 16
#define NGRP 6
#define NTHR (NGRP * 64)

// ---------------- scratch (__device__ globals: allowed) ----------------
__device__ __align__(16) float g_f1n [BB*N1*64];
__device__ __align__(16) float g_f2n [BB*N2*64];
__device__ __align__(16) float g_p2r [BB*N2*64];
__device__ __align__(16) float g_p2ro[BB*N2*64];
__device__ __align__(16) float g_p2z [BB*N2*64];
__device__ __align__(16) float g_gp1r[BB*N1*64];
__device__ __align__(16) float g_gp1z[BB*N1*64];
__device__ __align__(16) float g_p1o [BB*N1*64];
__device__ float g_cosv[BB*N1*NSPLIT*8];
__device__ int   g_cosi[BB*N1*NSPLIT*8];
__device__ float g_eucv[BB*N1*NSPLIT*8];
__device__ int   g_euci[BB*N1*NSPLIT*8];

// ---------------- helpers ----------------
__device__ __forceinline__ void fma2(unsigned long long& d, unsigned long long a, unsigned long long b) {
    asm("fma.rn.f32x2 %0, %1, %2, %0;" : "+l"(d) : "l"(a), "l"(b));
}
__device__ __forceinline__ float hsum2(unsigned long long v) {
    return __uint_as_float((unsigned)v) + __uint_as_float((unsigned)(v >> 32));
}
__device__ __forceinline__ float leaky(float x) { return fmaxf(x, 0.1f * x); }
__device__ __forceinline__ float sigm(float x) { return 1.f / (1.f + __expf(-x)); }

__device__ __forceinline__ unsigned smem_u32(const void* p) {
    unsigned r;
    asm("{ .reg .u64 t; cvta.to.shared.u64 t, %1; cvt.u32.u64 %0, t; }" : "=r"(r) : "l"(p));
    return r;
}
__device__ __forceinline__ void cp16(float* dst, const float* src) {
    asm volatile("cp.async.ca.shared.global [%0], [%1], 16;"
                 :: "r"(smem_u32(dst)), "l"(src) : "memory");
}
#define CP_COMMIT_WAIT() asm volatile("cp.async.commit_group;\n\tcp.async.wait_group 0;" ::: "memory")

__device__ __forceinline__ void top8_insert(float (&tv)[8], int (&ti)[8], float v, int j) {
    #pragma unroll
    for (int t = 0; t < 8; t++) {
        if (v > tv[t]) { float fv = tv[t]; int fj = ti[t]; tv[t] = v; ti[t] = j; v = fv; j = fj; }
    }
}

// load one 64-float weight row (68-float padded) from smem into registers
__device__ __forceinline__ void loadrow(const float* __restrict__ W, int o, ulonglong2 (&w)[16]) {
    const ulonglong2* p = (const ulonglong2*)(W + o * 68);
    #pragma unroll
    for (int i = 0; i < 16; i++) w[i] = p[i];
}
// dot of register weight row with a 64-float smem vector (batched halves)
__device__ __forceinline__ float dotv64(const ulonglong2 (&w)[16], const float* __restrict__ v) {
    const ulonglong2* v2 = (const ulonglong2*)v;
    ulonglong2 x[8];
    unsigned long long a0 = 0ull, a1 = 0ull, a2 = 0ull, a3 = 0ull;
    #pragma unroll
    for (int i = 0; i < 8; i++) x[i] = v2[i];
    #pragma unroll
    for (int i = 0; i < 8; i += 2) {
        fma2(a0, w[i].x,     x[i].x);
        fma2(a1, w[i].y,     x[i].y);
        fma2(a2, w[i + 1].x, x[i + 1].x);
        fma2(a3, w[i + 1].y, x[i + 1].y);
    }
    #pragma unroll
    for (int i = 0; i < 8; i++) x[i] = v2[8 + i];
    #pragma unroll
    for (int i = 0; i < 8; i += 2) {
        fma2(a0, w[8 + i].x,     x[i].x);
        fma2(a1, w[8 + i].y,     x[i].y);
        fma2(a2, w[8 + i + 1].x, x[i + 1].x);
        fma2(a3, w[8 + i + 1].y, x[i + 1].y);
    }
    return (hsum2(a0) + hsum2(a1)) + (hsum2(a2) + hsum2(a3));
}
// dot of a gmem weight row (64 consecutive floats) with a 64-float smem vector
__device__ __forceinline__ float gdot64(const float* __restrict__ Wrow, const float* __restrict__ v) {
    const float4* w4 = (const float4*)Wrow;
    const float4* v4 = (const float4*)v;
    float a0 = 0.f, a1 = 0.f, a2 = 0.f, a3 = 0.f;
    #pragma unroll
    for (int i = 0; i < 16; i += 4) {
        float4 w = __ldg(&w4[i]);      float4 x = v4[i];
        a0 += w.x * x.x + w.y * x.y + w.z * x.z + w.w * x.w;
        float4 w1 = __ldg(&w4[i + 1]); float4 x1 = v4[i + 1];
        a1 += w1.x * x1.x + w1.y * x1.y + w1.z * x1.z + w1.w * x1.w;
        float4 w2 = __ldg(&w4[i + 2]); float4 x2 = v4[i + 2];
        a2 += w2.x * x2.x + w2.y * x2.y + w2.z * x2.z + w2.w * x2.w;
        float4 w3 = __ldg(&w4[i + 3]); float4 x3 = v4[i + 3];
        a3 += w3.x * x3.x + w3.y * x3.y + w3.z * x3.z + w3.w * x3.w;
    }
    return (a0 + a1) + (a2 + a3);
}

// ---------------- [0] normalize both knn tensors in one launch ----------------
__global__ void k_norm_both(const float* __restrict__ knn1, const float* __restrict__ knn2,
                            float* __restrict__ f1n, float* __restrict__ f2n) {
    __shared__ float s[64 * 65];
    __shared__ float inv[64];
    int bx = blockIdx.x, b = blockIdx.y;
    const float* src; float* dst; int N, n0;
    if (bx < N1 / 64) { src = knn1; dst = f1n; N = N1; n0 = bx * 64; }
    else              { src = knn2; dst = f2n; N = N2; n0 = (bx - N1 / 64) * 64; }
    src += (size_t)b * 64 * N;
    for (int i = threadIdx.x; i < 4096; i += 256) {
        int c = i >> 6, n = i & 63;
        s[c * 65 + n] = src[(size_t)c * N + n0 + n];
    }
    __syncthreads();
    if (threadIdx.x < 64) {
        int n = threadIdx.x;
        float acc = 0.f;
        #pragma unroll
        for (int c = 0; c < 64; c++) { float v = s[c * 65 + n]; acc += v * v; }
        inv[n] = rsqrtf(acc + 1e-8f);
    }
    __syncthreads();
    dst += ((size_t)b * N + n0) * 64;
    for (int i = threadIdx.x; i < 4096; i += 256) {
        int n = i >> 6, c = i & 63;
        dst[n * 64 + c] = s[c * 65 + n] * inv[n];
    }
}

// ---------------- [1] fused cos + euc knn partials (proven inner loops) ----------------
__global__ void __launch_bounds__(128) k_knn_both(const float* __restrict__ xyz1, const float* __restrict__ xyz2) {
    __shared__ __align__(16) float sh[64 * 68];
    int b = blockIdx.z, yy = blockIdx.y;
    int q = blockIdx.x * 128 + threadIdx.x;

    if (yy < 8) {
        int split = yy;
        ulonglong2 qr[16];
        const ulonglong2* qp = (const ulonglong2*)(g_f1n + ((size_t)b * N1 + q) * 64);
        #pragma unroll
        for (int i = 0; i < 16; i++) qr[i] = qp[i];
        float tv[8]; int ti[8];
        #pragma unroll
        for (int i = 0; i < 8; i++) { tv[i] = -1e30f; ti[i] = 0; }
        const int SPLITN = N2 / NSPLIT;
        int j0 = split * SPLITN;
        for (int tile = 0; tile < SPLITN / 64; tile++) {
            int jt = j0 + tile * 64;
            __syncthreads();
            for (int i = threadIdx.x; i < 4096; i += 128) {
                int cand = i >> 6, c = i & 63;
                sh[cand * 68 + c] = g_f2n[((size_t)b * N2 + jt + cand) * 64 + c];
            }
            __syncthreads();
            for (int cc = 0; cc < 64; cc++) {
                const ulonglong2* cp = (const ulonglong2*)(sh + cc * 68);
                unsigned long long a0 = 0ull, a1 = 0ull, a2 = 0ull, a3 = 0ull;
                #pragma unroll
                for (int i = 0; i < 16; i += 2) {
                    ulonglong2 c2 = cp[i];
                    fma2(a0, qr[i].x, c2.x);
                    fma2(a1, qr[i].y, c2.y);
                    ulonglong2 c3 = cp[i + 1];
                    fma2(a2, qr[i + 1].x, c3.x);
                    fma2(a3, qr[i + 1].y, c3.y);
                }
                float d = (hsum2(a0) + hsum2(a1)) + (hsum2(a2) + hsum2(a3));
                if (d > tv[7]) top8_insert(tv, ti, d, jt + cc);
            }
        }
        size_t base = (((size_t)b * N1 + q) * NSPLIT + split) * 8;
        #pragma unroll
        for (int t = 0; t < 8; t++) { g_cosv[base + t] = tv[t]; g_cosi[base + t] = ti[t]; }
    } else {
        int split = yy - 8;
        float* sx = sh; float* sy = sh + 1024; float* sz = sh + 2048;
        int j0 = split * 1024;
        const float* x2 = xyz2 + (size_t)b * 3 * N2;
        for (int i = threadIdx.x; i < 1024; i += 128) {
            sx[i] = x2[j0 + i]; sy[i] = x2[N2 + j0 + i]; sz[i] = x2[2 * N2 + j0 + i];
        }
        __syncthreads();
        const float* x1 = xyz1 + (size_t)b * 3 * N1;
        float qx = x1[q], qy = x1[N1 + q], qz = x1[2 * N1 + q];
        float tv[8]; int ti[8];
        #pragma unroll
        for (int i = 0; i < 8; i++) { tv[i] = -1e30f; ti[i] = 0; }
        for (int cc = 0; cc < 1024; cc++) {
            float dx = sx[cc] - qx, dy = sy[cc] - qy, dz = sz[cc] - qz;
            float d = -(dx * dx + dy * dy + dz * dz);
            if (d > tv[7]) top8_insert(tv, ti, d, j0 + cc);
        }
        size_t base = (((size_t)b * N1 + q) * NSPLIT + split) * 8;
        #pragma unroll
        for (int t = 0; t < 8; t++) { g_eucv[base + t] = tv[t]; g_euci[base + t] = ti[t]; }
    }
}

// ---------------- [2] all 6 projections in one launch (blockIdx.z selects variant) ----------------
__global__ void __launch_bounds__(256) k_projall(
    const float* __restrict__ points1, const float* __restrict__ points2,
    const float* __restrict__ Wfr2, const float* __restrict__ Wfro2, const float* __restrict__ Wfz2,
    const float* __restrict__ Wfr,  const float* __restrict__ Wfz,   const float* __restrict__ Wfro,
    float* __restrict__ p2r, float* __restrict__ p2ro, float* __restrict__ p2z,
    float* __restrict__ gp1r, float* __restrict__ gp1z, float* __restrict__ p1o)
{
    __shared__ __align__(16) float s[64 * 68];
    __shared__ __align__(16) float Wsh[64 * 68];
    int m = blockIdx.z;
    const float* P; const float* W; float* out; int N;
    if (m < 3) {
        P = points2; N = N2;
        W   = (m == 0) ? Wfr2 : ((m == 1) ? Wfro2 : Wfz2);
        out = (m == 0) ? p2r  : ((m == 1) ? p2ro  : p2z);
    } else {
        P = points1; N = N1;
        W   = (m == 3) ? Wfr  : ((m == 4) ? Wfz  : Wfro);
        out = (m == 3) ? gp1r : ((m == 4) ? gp1z : p1o);
    }
    if (blockIdx.x * 64 >= N) return;
    int b = blockIdx.y;
    int n0 = blockIdx.x * 64;
    int t = threadIdx.x;
    for (int i = t; i < 4096; i += 256) {
        int c = i >> 6, n = i & 63;
        s[n * 68 + c] = P[((size_t)b * 64 + c) * N + n0 + n];
        Wsh[(i >> 6) * 68 + (i & 63)] = W[i];
    }
    __syncthreads();
    int o = t & 63, nb = t >> 6;
    float acc[16];
    #pragma unroll
    for (int j = 0; j < 16; j++) acc[j] = 0.f;
    const float4* w4 = (const float4*)(Wsh + o * 68);
    #pragma unroll
    for (int ci = 0; ci < 16; ci++) {
        float4 w = w4[ci];
        #pragma unroll
        for (int j = 0; j < 16; j++) {
            float4 v = ((const float4*)(s + (nb + 4 * j) * 68))[ci];
            acc[j] += w.x * v.x + w.y * v.y + w.z * v.z + w.w * v.w;
        }
    }
    float* dst = out + ((size_t)b * N + n0) * 64;
    #pragma unroll
    for (int j = 0; j < 16; j++)
        dst[(nb + 4 * j) * 64 + o] = acc[j];
}

// ---------------- [3] fused merge + GRU-mapping MLP ----------------
// Streamed weights in a DOUBLE-BUFFERED slab filled by cp.async (prefetch of the
// next pass's matrix overlaps the current pass's compute). One barrier per pass.
__device__ __forceinline__ void slab_fetch(float* slab, const float* __restrict__ W, int tid) {
    for (int i = tid; i < 1024; i += NTHR) {
        int r = i * 4;
        cp16(&slab[(r >> 6) * 68 + (r & 63)], W + r);
    }
}

__global__ void __launch_bounds__(NTHR, 2) k_mlp(
    const float* __restrict__ xyz1, const float* __restrict__ xyz2,
    const float* __restrict__ Wr0, const float* __restrict__ br0,
    const float* __restrict__ Wr1, const float* __restrict__ br1,
    const float* __restrict__ Wr2, const float* __restrict__ br2,
    const float* __restrict__ Wz0, const float* __restrict__ bz0,
    const float* __restrict__ Wz1, const float* __restrict__ bz1,
    const float* __restrict__ Wz2, const float* __restrict__ bz2,
    const float* __restrict__ Wh0, const float* __restrict__ bh0,
    const float* __restrict__ Wh1, const float* __restrict__ bh1,
    const float* __restrict__ Wh2, const float* __restrict__ bh2,
    float* __restrict__ out)
{
    extern __shared__ __align__(16) float dsm[];
    float* SLAB0 = dsm;               // 4352 floats each, rows padded to 68
    float* SLAB1 = dsm + 4352;
    float* GBUF  = dsm + 8704;        // NGRP groups x 3 buffers x 16*64
    __shared__ int sIdx[NGRP * 16];

    int tid = threadIdx.x;
    int g = tid >> 6, o = tid & 63;

    int q = blockIdx.x * NGRP + g;
    if (q > BB * N1 - 1) q = BB * N1 - 1;   // tail clamp: duplicate deterministic work
    int b = q >> 12, n = q & 4095;

    // ---- merge partial top-8 lists (lane 0 of each warp; 2 warps per group) ----
    if ((o & 31) == 0) {
        int half = o >> 5;             // warp0: cosine, warp1: euclidean
        const float* pv = half ? g_eucv : g_cosv;
        const int*   pi = half ? g_euci : g_cosi;
        size_t base = (size_t)q * 64;
        float tv[8]; int ti[8];
        #pragma unroll
        for (int i = 0; i < 8; i++) { tv[i] = -1e30f; ti[i] = 0; }
        #pragma unroll 4
        for (int i = 0; i < 64; i++) {
            float v = pv[base + i];
            if (v > tv[7]) top8_insert(tv, ti, v, pi[base + i]);
        }
        #pragma unroll
        for (int t = 0; t < 8; t++) sIdx[g * 16 + half * 8 + t] = ti[t];
    }
    __syncthreads();   // sIdx ready

    // startup: async-fetch first weight matrix while stage A computes
    slab_fetch(SLAB0, Wz1, tid);

    float wr0x = Wr0[o * 3], wr0y = Wr0[o * 3 + 1], wr0z = Wr0[o * 3 + 2];
    float wz0x = Wz0[o * 3], wz0y = Wz0[o * 3 + 1], wz0z = Wz0[o * 3 + 2];
    float wh0x = Wh0[o * 3], wh0y = Wh0[o * 3 + 1], wh0z = Wh0[o * 3 + 2];
    float br0o = br0[o], br1o = br1[o], br2o = br2[o];
    float bz0o = bz0[o], bz1o = bz1[o];
    float bh0o = bh0[o], bh1o = bh1[o];
    size_t nb = (size_t)b * N1 + n;
    float gp1ro = g_gp1r[nb * 64 + o];
    float gp1zo = g_gp1z[nb * 64 + o];
    float p1oo  = g_p1o [nb * 64 + o];
    float x1x = xyz1[(b * 3 + 0) * N1 + n];
    float x1y = xyz1[(b * 3 + 1) * N1 + n];
    float x1z = xyz1[(b * 3 + 2) * N1 + n];

    float* T = GBUF + g * 3072;   // t0[k][o]; tail: zmax/hmax vectors
    float* U = T + 1024;          // u0[k][o] -> t1[k][o]
    float* V = U + 1024;          // h partial -> v0[k][o]

    // ---- Stage A: elementwise layer-0 for all k ----
    #pragma unroll 2
    for (int k = 0; k < KSEL; k++) {
        int j = sIdx[g * 16 + k];
        size_t gb = ((size_t)b * N2 + j) * 64 + o;
        float gr  = g_p2r [gb];
        float gro = g_p2ro[gb];
        float gz  = g_p2z [gb];
        float dx = __ldg(&xyz2[(b * 3 + 0) * N2 + j]) - x1x;
        float dy = __ldg(&xyz2[(b * 3 + 1) * N2 + j]) - x1y;
        float dz = __ldg(&xyz2[(b * 3 + 2) * N2 + j]) - x1z;
        T[k * 64 + o] = leaky(fmaf(wr0x, dx, fmaf(wr0y, dy, fmaf(wr0z, dz, br0o + gp1ro + gr))));
        U[k * 64 + o] = leaky(fmaf(wz0x, dx, fmaf(wz0y, dy, fmaf(wz0z, dz, bz0o + gp1zo + gro))));
        V[k * 64 + o] = fmaf(wh0x, dx, fmaf(wh0y, dy, fmaf(wh0z, dz, bh0o + gz)));
    }
    CP_COMMIT_WAIT();
    __syncthreads();   // stage A visible + SLAB0 (WZ1) ready

    ulonglong2 w[16];
    float zmax = -1e30f, hmax = -1e30f;

    // ---- pass 0: WZ1 (SLAB0) -> zmax from U; prefetch WR1 -> SLAB1 ----
    slab_fetch(SLAB1, Wr1, tid);
    loadrow(SLAB0, o, w);
    #pragma unroll 1
    for (int k = 0; k < KSEL; k++)
        zmax = fmaxf(zmax, leaky(dotv64(w, U + k * 64) + bz1o));
    CP_COMMIT_WAIT();
    __syncthreads();   // U reads done; SLAB1 ready

    // ---- pass 1: WR1 (SLAB1) -> U <- t1 from T; prefetch WR2 -> SLAB0 ----
    slab_fetch(SLAB0, Wr2, tid);
    loadrow(SLAB1, o, w);
    #pragma unroll 1
    for (int k = 0; k < KSEL; k++)
        U[k * 64 + o] = leaky(dotv64(w, T + k * 64) + br1o);
    CP_COMMIT_WAIT();
    __syncthreads();   // t1 visible; SLAB0 ready

    // ---- pass 2: WR2 (SLAB0) -> r from t1, update V; prefetch WH1 -> SLAB1 ----
    slab_fetch(SLAB1, Wh1, tid);
    loadrow(SLAB0, o, w);
    #pragma unroll 1
    for (int k = 0; k < KSEL; k++) {
        float r = sigm(dotv64(w, U + k * 64) + br2o);
        V[k * 64 + o] = leaky(fmaf(r, p1oo, V[k * 64 + o]));
    }
    CP_COMMIT_WAIT();
    __syncthreads();   // V updates visible; SLAB1 ready

    // ---- pass 3: WH1 (SLAB1) -> hmax from V ----
    loadrow(SLAB1, o, w);
    #pragma unroll 1
    for (int k = 0; k < KSEL; k++)
        hmax = fmaxf(hmax, leaky(dotv64(w, V + k * 64) + bh1o));

    T[o] = zmax;
    T[64 + o] = hmax;
    __syncthreads();   // zmax/hmax vectors visible

    // ---- final layer: weights from gmem (L1-hot) ----
    float z = sigm(gdot64(Wz2 + o * 64, T) + bz2[o]);
    float h = leaky(gdot64(Wh2 + o * 64, T + 64) + bh2[o]);
    out[((size_t)b * 64 + o) * N1 + n] = (1.f - z) * p1oo + z * h;
}

// ---------------- launch ----------------
extern "C" void kernel_launch(void* const* d_in, const int* in_sizes, int n_in,
                              void* d_out, int out_size) {
    (void)in_sizes; (void)n_in; (void)out_size;
    const float* xyz1    = (const float*)d_in[0];
    const float* xyz2    = (const float*)d_in[1];
    const float* points1 = (const float*)d_in[2];
    const float* points2 = (const float*)d_in[3];
    const float* knn1    = (const float*)d_in[4];
    const float* knn2    = (const float*)d_in[5];
    const float* Wfr   = (const float*)d_in[6];
    const float* Wfro  = (const float*)d_in[7];
    const float* Wfz   = (const float*)d_in[8];
    const float* Wfr2  = (const float*)d_in[9];
    const float* Wfro2 = (const float*)d_in[10];
    const float* Wfz2  = (const float*)d_in[11];
    const float* Wr0 = (const float*)d_in[12]; const float* br0 = (const float*)d_in[13];
    const float* Wr1 = (const float*)d_in[14]; const float* br1 = (const float*)d_in[15];
    const float* Wr2 = (const float*)d_in[16]; const float* br2 = (const float*)d_in[17];
    const float* Wz0 = (const float*)d_in[18]; const float* bz0 = (const float*)d_in[19];
    const float* Wz1 = (const float*)d_in[20]; const float* bz1 = (const float*)d_in[21];
    const float* Wz2 = (const float*)d_in[22]; const float* bz2 = (const float*)d_in[23];
    const float* Wh0 = (const float*)d_in[24]; const float* bh0 = (const float*)d_in[25];
    const float* Wh1 = (const float*)d_in[26]; const float* bh1 = (const float*)d_in[27];
    const float* Wh2 = (const float*)d_in[28]; const float* bh2 = (const float*)d_in[29];
    float* out = (float*)d_out;

    float *f1n, *f2n, *p2r, *p2ro, *p2z, *gp1r, *gp1z, *p1o;
    cudaGetSymbolAddress((void**)&f1n,  g_f1n);
    cudaGetSymbolAddress((void**)&f2n,  g_f2n);
    cudaGetSymbolAddress((void**)&p2r,  g_p2r);
    cudaGetSymbolAddress((void**)&p2ro, g_p2ro);
    cudaGetSymbolAddress((void**)&p2z,  g_p2z);
    cudaGetSymbolAddress((void**)&gp1r, g_gp1r);
    cudaGetSymbolAddress((void**)&gp1z, g_gp1z);
    cudaGetSymbolAddress((void**)&p1o,  g_p1o);

    const int MLP_SMEM = (2 * 4352 + NGRP * 3 * 1024) * 4;  // 108544 B -> 2 blocks/SM
    cudaFuncSetAttribute(k_mlp, cudaFuncAttributeMaxDynamicSharedMemorySize, MLP_SMEM);

    // [0] normalize both knn tensors
    k_norm_both<<<dim3((N1 + N2) / 64, BB), 256>>>(knn1, knn2, f1n, f2n);
    // [1] fused cos+euc knn partials (proven)
    k_knn_both<<<dim3(N1 / 128, 16, BB), 128>>>(xyz1, xyz2);
    // [2] all projections
    k_projall<<<dim3(N2 / 64, BB, 6), 256>>>(points1, points2,
        Wfr2, Wfro2, Wfz2, Wfr, Wfz, Wfro,
        p2r, p2ro, p2z, gp1r, gp1z, p1o);
    // [3] fused merge + GRU MLP (capture slot; cp.async double-buffered slab)
    int nblk = (BB * N1 + NGRP - 1) / NGRP;
    k_mlp<<<nblk, NTHR, MLP_SMEM>>>(
        xyz1, xyz2,
        Wr0, br0, Wr1, br1, Wr2, br2,
        Wz0, bz0, Wz1, bz1, Wz2, bz2,
        Wh0, bh0, Wh1, bh1, Wh2, bh2,
        out);
}